// round 11
// baseline (speedup 1.0000x reference)
#include <cuda_runtime.h>
#include <cuda.h>
#include <cuda_fp16.h>
#include <cstdint>

// ---------------- problem constants ----------------
#define NTOK   16384
#define DIN    512
#define DOUT   512
#define KEXP   8
#define KC     64              // fp16 elems per K chunk = 128 B (SW128 atom)
#define TILE_M 128
#define TILE_N 64
#define EPC    2               // experts per CTA (kz = 4)
#define NCHJ   8               // K chunks per expert (512/64)
#define A_BYTES  (TILE_M * 128)     // 16 KB
#define B_BYTES  (TILE_N * 128)     // 8 KB
#define NSA      2                  // A ring stages
#define NSB      4                  // B ring stages (2 groups x 2 experts)
#define DYN_BYTES (NSA * A_BYTES + NSB * B_BYTES + 1024)   // ~65 KB -> 3 CTAs/SM

// ---------------- device scratch ----------------
__device__ __half g_xh[(size_t)NTOK * DIN];        // fp16 unscaled x
__device__ float  g_coeffs[NTOK * KEXP];           // gating coeffs
__device__ __half g_wc[(size_t)DOUT * (KEXP*DIN)]; // fp16 stacked weights [o][e*512+i]

// ---------------- PTX helpers (sm_90-baseline; NO tcgen05) ----------------
__device__ __forceinline__ uint32_t smem_u32(const void* p) {
    uint32_t a;
    asm("{ .reg .u64 t; cvta.to.shared.u64 t, %1; cvt.u32.u64 %0, t; }" : "=r"(a) : "l"(p));
    return a;
}

#define MBAR_INIT(addr, cnt) \
    asm volatile("mbarrier.init.shared.b64 [%0], %1;" :: "r"(addr), "r"(cnt) : "memory")
#define MBAR_EXPECT_TX(addr, bytes) \
    asm volatile("mbarrier.arrive.expect_tx.shared.b64 _, [%0], %1;" :: "r"(addr), "r"(bytes) : "memory")
#define MBAR_ARRIVE(addr) \
    asm volatile("mbarrier.arrive.shared.b64 _, [%0];" :: "r"(addr) : "memory")

#define MBAR_WAIT(addr, parity) do {                                              \
    uint32_t _m = (uint32_t)(addr);                                               \
    uint32_t _p = (uint32_t)(parity);                                             \
    uint32_t _done;                                                               \
    asm volatile("{\n\t.reg .pred p;\n\t"                                         \
        "mbarrier.try_wait.parity.acquire.cta.shared::cta.b64 p, [%1], %2;\n\t"   \
        "selp.b32 %0, 1, 0, p;\n\t}"                                              \
        : "=r"(_done) : "r"(_m), "r"(_p) : "memory");                             \
    if (!_done) {                                                                 \
        asm volatile("{\n\t.reg .pred P1;\n\t"                                    \
            "WAIT_LOOP_%=:\n\t"                                                   \
            "mbarrier.try_wait.parity.acquire.cta.shared::cta.b64 P1, [%0], %1, 0x989680;\n\t" \
            "@P1 bra.uni WAIT_DONE_%=;\n\t"                                       \
            "bra.uni WAIT_LOOP_%=;\n\t"                                           \
            "WAIT_DONE_%=:\n\t}"                                                  \
            :: "r"(_m), "r"(_p) : "memory");                                      \
    }                                                                             \
} while (0)

#define TMA2D(dst, map, cx, cy, bar) \
    asm volatile("cp.async.bulk.tensor.2d.shared::cta.global.tile.mbarrier::complete_tx::bytes " \
        "[%0], [%1, {%2, %3}], [%4];" \
        :: "r"(dst), "l"(map), "r"(cx), "r"(cy), "r"(bar) : "memory")

#define LDSM_X4(r, addr) \
    asm volatile("ldmatrix.sync.aligned.m8n8.x4.shared.b16 {%0,%1,%2,%3}, [%4];" \
        : "=r"((r)[0]), "=r"((r)[1]), "=r"((r)[2]), "=r"((r)[3]) : "r"(addr))

__device__ __forceinline__ uint32_t hmul2(uint32_t a, uint32_t b) {
    uint32_t d;
    asm("mul.rn.f16x2 %0, %1, %2;" : "=r"(d) : "r"(a), "r"(b));
    return d;
}

__device__ __forceinline__ void mma16816(float* d, const uint32_t* a, const uint32_t* b) {
    asm volatile("mma.sync.aligned.m16n8k16.row.col.f32.f16.f16.f32 "
        "{%0,%1,%2,%3}, {%4,%5,%6,%7}, {%8,%9}, {%0,%1,%2,%3};"
        : "+f"(d[0]), "+f"(d[1]), "+f"(d[2]), "+f"(d[3])
        : "r"(a[0]), "r"(a[1]), "r"(a[2]), "r"(a[3]), "r"(b[0]), "r"(b[1]));
}

// ---------------- kernel 1: gating softmax (fp32) + fp16 convert of x ----------------
__global__ void __launch_bounds__(256) prep_x_kernel(
    const float* __restrict__ x,
    const float* __restrict__ mixer_w,
    const float* __restrict__ mixer_b)
{
    __shared__ float sw[KEXP * DIN];
    __shared__ float sb[KEXP];
    const int tid = threadIdx.x;
    for (int i = tid; i < KEXP * DIN; i += 256) sw[i] = mixer_w[i];
    if (tid < KEXP) sb[tid] = mixer_b[tid];
    __syncthreads();

    const int warp = tid >> 5, lane = tid & 31;
    const int t = blockIdx.x * 8 + warp;
    const float2* xr2 = reinterpret_cast<const float2*>(x + (size_t)t * DIN);

    float2 xv[8];
    #pragma unroll
    for (int ii = 0; ii < 8; ii++) xv[ii] = xr2[ii * 32 + lane];

    float acc[KEXP];
    #pragma unroll
    for (int e = 0; e < KEXP; e++) acc[e] = 0.f;
    #pragma unroll
    for (int ii = 0; ii < 8; ii++) {
        const int i = ii * 64 + lane * 2;
        #pragma unroll
        for (int e = 0; e < KEXP; e++)
            acc[e] += xv[ii].x * sw[e * DIN + i] + xv[ii].y * sw[e * DIN + i + 1];
    }
    #pragma unroll
    for (int off = 16; off > 0; off >>= 1) {
        #pragma unroll
        for (int e = 0; e < KEXP; e++)
            acc[e] += __shfl_xor_sync(0xffffffffu, acc[e], off);
    }
    float lg[KEXP];
    #pragma unroll
    for (int e = 0; e < KEXP; e++) lg[e] = acc[e] + sb[e];
    float mx = lg[0];
    #pragma unroll
    for (int e = 1; e < KEXP; e++) mx = fmaxf(mx, lg[e]);
    float p[KEXP], s = 0.f;
    #pragma unroll
    for (int e = 0; e < KEXP; e++) { p[e] = __expf(lg[e] - mx); s += p[e]; }
    const float inv = 1.f / s;

    __half2* dst = reinterpret_cast<__half2*>(g_xh + (size_t)t * DIN);
    #pragma unroll
    for (int ii = 0; ii < 8; ii++)
        dst[ii * 32 + lane] = __floats2half2_rn(xv[ii].x, xv[ii].y);

    #pragma unroll
    for (int e = 0; e < KEXP; e++)
        if (lane == e) g_coeffs[(size_t)t * KEXP + e] = p[e] * inv;
}

// ---------------- kernel 2: pack stacked weights to fp16 + zero output ----------------
__global__ void __launch_bounds__(256) prep_w_kernel(const float* __restrict__ W,
                                                     float4* __restrict__ out4) {
    const int o = blockIdx.x;
    const int tid = threadIdx.x;
    __half* orow = g_wc + (size_t)o * (KEXP * DIN);
    #pragma unroll
    for (int e = 0; e < KEXP; e++) {
        const float* src = W + ((size_t)e * DOUT + o) * DIN;
        for (int i = tid; i < DIN; i += 256)
            orow[e * DIN + i] = __float2half_rn(src[i]);
    }
    // zero the output (split-expert atomics land on it): 2.1M float4 / 512 blocks
    const size_t base = (size_t)o * 4096 + tid;
    #pragma unroll
    for (int i = 0; i < 16; i++)
        out4[base + i * 256] = make_float4(0.f, 0.f, 0.f, 0.f);
}

// ---------------- kernel 3: fused 2-expert GEMM, per-expert A-frag scaling, 3 CTAs/SM --------
// acc accumulates Sigma_e c_e*(A B_e^T) directly into ONE fp32 accumulator.
// Bias added exactly (fp32) in epilogue; 4 kz quarters reduced via deterministic atomicAdds.
__global__ void __launch_bounds__(256, 3) moe_gemm_kernel(
    const __grid_constant__ CUtensorMap a_map,     // g_xh  [16384, 512]
    const __grid_constant__ CUtensorMap b_map,     // g_wc  [512, 4096]
    const float* __restrict__ bz,                  // [8, 512]
    float* __restrict__ out)
{
    extern __shared__ char dyn_smem[];
    __shared__ __align__(8) unsigned long long s_bars[2 * NSA + 2 * NSB];
    __shared__ float s_coef[TILE_M * EPC];         // [128][2] this CTA's experts
    __shared__ float s_bias[EPC * TILE_N];         // [2][64]

    const int tid = threadIdx.x;
    const int w   = tid >> 5;
    const int l   = tid & 31;
    const int ntile = blockIdx.x;    // 0..7
    const int mtile = blockIdx.y;    // 0..127
    const int kz    = blockIdx.z;    // 0..3  -> experts kz*2, kz*2+1

    const uint32_t base = (smem_u32(dyn_smem) + 1023u) & ~1023u;
    const uint32_t As = base;                       // A ring: 2 x 16 KB
    const uint32_t Bs = base + NSA * A_BYTES;       // B ring: 4 x 8 KB
    const uint32_t bars = smem_u32(s_bars);
    const uint32_t AF = bars;                 // A full  [2]
    const uint32_t AE = bars + NSA * 8;       // A empty [2]
    const uint32_t BF = bars + 2 * NSA * 8;   // B full  [4]
    const uint32_t BE = BF + NSB * 8;         // B empty [4]

    if (tid == 0) {
        #pragma unroll
        for (int s = 0; s < NSA; s++) { MBAR_INIT(AF + s * 8, 1); MBAR_INIT(AE + s * 8, 8); }
        #pragma unroll
        for (int s = 0; s < NSB; s++) { MBAR_INIT(BF + s * 8, 1); MBAR_INIT(BE + s * 8, 8); }
    }
    for (int i = tid; i < TILE_M * EPC; i += 256)
        s_coef[i] = g_coeffs[(mtile * TILE_M + (i >> 1)) * KEXP + kz * EPC + (i & 1)];
    for (int i = tid; i < EPC * TILE_N; i += 256)
        s_bias[i] = bz[(kz * EPC + (i >> 6)) * DOUT + ntile * TILE_N + (i & 63)];
    __syncthreads();

    if (tid == 0) {
        #pragma unroll
        for (int s = 0; s < NSA; s++) {          // A chunks 0,1
            MBAR_EXPECT_TX(AF + s * 8, A_BYTES);
            TMA2D(As + s * A_BYTES, &a_map, s * KC, mtile * TILE_M, AF + s * 8);
        }
        #pragma unroll
        for (int bi = 0; bi < NSB; bi++) {       // B slot bi: chunk j=bi>>1, expert ei=bi&1
            MBAR_EXPECT_TX(BF + bi * 8, B_BYTES);
            TMA2D(Bs + bi * B_BYTES, &b_map,
                  ((kz * EPC + (bi & 1)) * NCHJ + (bi >> 1)) * KC, ntile * TILE_N, BF + bi * 8);
        }
    }

    // warp layout: 4 (M) x 2 (N); warp tile 32x32
    const int wm = (w & 3) * 32;
    const int wn = (w >> 2) * 32;
    int rA[2], rB[2];
    #pragma unroll
    for (int mi = 0; mi < 2; mi++) rA[mi] = wm + mi * 16 + (l & 15);
    #pragma unroll
    for (int nj2 = 0; nj2 < 2; nj2++)
        rB[nj2] = wn + nj2 * 16 + ((l >> 4) & 1) * 8 + (l & 7);
    const int segA = (l >> 4);
    const int segB = (l >> 3) & 1;

    // per-expert per-row half2 coeffs: ch[ei][mi][h]  row = wm+mi*16+(l>>2)+h*8
    uint32_t ch[EPC][2][2];
    #pragma unroll
    for (int ei = 0; ei < EPC; ei++)
        #pragma unroll
        for (int mi = 0; mi < 2; mi++)
            #pragma unroll
            for (int h = 0; h < 2; h++) {
                const int r = wm + mi * 16 + (l >> 2) + h * 8;
                const __half hv = __float2half_rn(s_coef[r * EPC + ei]);
                const __half2 h2 = __half2half2(hv);
                ch[ei][mi][h] = *reinterpret_cast<const uint32_t*>(&h2);
            }

    float acc[2][4][4];
    #pragma unroll
    for (int mi = 0; mi < 2; mi++)
        #pragma unroll
        for (int nj = 0; nj < 4; nj++)
            #pragma unroll
            for (int q = 0; q < 4; q++) acc[mi][nj][q] = 0.f;

    #pragma unroll 1
    for (int j = 0; j < NCHJ; j++) {
        const int sa   = j & 1;
        const int sgrp = (j & 1) * EPC;
        const uint32_t ph = (uint32_t)((j >> 1) & 1);
        const uint32_t Ab = As + sa * A_BYTES;

        MBAR_WAIT(AF + sa * 8, ph);
        #pragma unroll
        for (int ei = 0; ei < EPC; ei++) MBAR_WAIT(BF + (sgrp + ei) * 8, ph);

        #pragma unroll
        for (int kk = 0; kk < 4; kk++) {
            const int s0 = kk * 2;
            uint32_t ar[2][4];
            #pragma unroll
            for (int mi = 0; mi < 2; mi++) {
                uint32_t addr = Ab + rA[mi] * 128 +
                    ((uint32_t)((s0 + segA) ^ (rA[mi] & 7)) << 4);
                LDSM_X4(ar[mi], addr);
            }
            #pragma unroll
            for (int ei = 0; ei < EPC; ei++) {
                const uint32_t Bb = Bs + (sgrp + ei) * B_BYTES;
                uint32_t br[2][4];
                #pragma unroll
                for (int nj2 = 0; nj2 < 2; nj2++) {
                    uint32_t addr = Bb + rB[nj2] * 128 +
                        ((uint32_t)((s0 + segB) ^ (rB[nj2] & 7)) << 4);
                    LDSM_X4(br[nj2], addr);
                }
                #pragma unroll
                for (int mi = 0; mi < 2; mi++) {
                    uint32_t as[4];
                    as[0] = hmul2(ar[mi][0], ch[ei][mi][0]);
                    as[1] = hmul2(ar[mi][1], ch[ei][mi][1]);
                    as[2] = hmul2(ar[mi][2], ch[ei][mi][0]);
                    as[3] = hmul2(ar[mi][3], ch[ei][mi][1]);
                    #pragma unroll
                    for (int nj = 0; nj < 4; nj++)
                        mma16816(acc[mi][nj], as, &br[nj >> 1][(nj & 1) * 2]);
                }
            }
        }

        if (l == 0) {
            MBAR_ARRIVE(AE + sa * 8);
            #pragma unroll
            for (int ei = 0; ei < EPC; ei++) MBAR_ARRIVE(BE + (sgrp + ei) * 8);
        }
        if (tid == 0 && j + 2 < NCHJ) {
            const int jn = j + 2;
            MBAR_WAIT(AE + sa * 8, ph);
            MBAR_EXPECT_TX(AF + sa * 8, A_BYTES);
            TMA2D(Ab, &a_map, jn * KC, mtile * TILE_M, AF + sa * 8);
            #pragma unroll
            for (int ei = 0; ei < EPC; ei++) {
                MBAR_WAIT(BE + (sgrp + ei) * 8, ph);
                MBAR_EXPECT_TX(BF + (sgrp + ei) * 8, B_BYTES);
                TMA2D(Bs + (sgrp + ei) * B_BYTES, &b_map,
                      ((kz * EPC + ei) * NCHJ + jn) * KC, ntile * TILE_N, BF + (sgrp + ei) * 8);
            }
        }
    }

    // epilogue: + Sigma_e c_e(row)*b_e(col) in fp32, then 4-way split-expert atomic reduce
    const int row0 = mtile * TILE_M + wm + (l >> 2);
    const int col0 = ntile * TILE_N + wn + 2 * (l & 3);
    #pragma unroll
    for (int mi = 0; mi < 2; mi++) {
        const int rl = wm + mi * 16 + (l >> 2);
        float cl[EPC], chh[EPC];
        #pragma unroll
        for (int e = 0; e < EPC; e++) {
            cl[e]  = s_coef[rl * EPC + e];
            chh[e] = s_coef[(rl + 8) * EPC + e];
        }
        #pragma unroll
        for (int nj = 0; nj < 4; nj++) {
            const int cc = wn + nj * 8 + 2 * (l & 3);
            float bl0 = 0.f, bl1 = 0.f, bh0 = 0.f, bh1 = 0.f;
            #pragma unroll
            for (int e = 0; e < EPC; e++) {
                const float b0 = s_bias[e * TILE_N + cc];
                const float b1 = s_bias[e * TILE_N + cc + 1];
                bl0 += cl[e] * b0;  bl1 += cl[e] * b1;
                bh0 += chh[e] * b0; bh1 += chh[e] * b1;
            }
            const int gr = row0 + mi * 16;
            const int gc = col0 + nj * 8;
            atomicAdd(&out[(size_t)gr * DOUT + gc],           acc[mi][nj][0] + bl0);
            atomicAdd(&out[(size_t)gr * DOUT + gc + 1],       acc[mi][nj][1] + bl1);
            atomicAdd(&out[(size_t)(gr + 8) * DOUT + gc],     acc[mi][nj][2] + bh0);
            atomicAdd(&out[(size_t)(gr + 8) * DOUT + gc + 1], acc[mi][nj][3] + bh1);
        }
    }
}

// ---------------- host launcher ----------------
typedef CUresult (*PFN_tmapEncode)(
    CUtensorMap*, CUtensorMapDataType, cuuint32_t, void*,
    const cuuint64_t*, const cuuint64_t*, const cuuint32_t*, const cuuint32_t*,
    CUtensorMapInterleave, CUtensorMapSwizzle, CUtensorMapL2promotion, CUtensorMapFloatOOBfill);

extern "C" void kernel_launch(void* const* d_in, const int* in_sizes, int n_in,
                              void* d_out, int out_size)
{
    const float* x  = (const float*)d_in[0];   // [16384, 512]
    const float* W  = (const float*)d_in[1];   // [8, 512, 512]
    const float* bz = (const float*)d_in[2];   // [8, 512]
    const float* mw = (const float*)d_in[3];   // [8, 512]
    const float* mb = (const float*)d_in[4];   // [8]
    float* out = (float*)d_out;
    (void)in_sizes; (void)n_in; (void)out_size;

    void* xh_ptr = nullptr; void* wc_ptr = nullptr;
    cudaGetSymbolAddress(&xh_ptr, g_xh);
    cudaGetSymbolAddress(&wc_ptr, g_wc);

    prep_x_kernel<<<NTOK / 8, 256>>>(x, mw, mb);
    prep_w_kernel<<<DOUT, 256>>>(W, (float4*)out);   // also zeroes out

    void* fnp = nullptr;
    cudaDriverEntryPointQueryResult st;
    cudaGetDriverEntryPointByVersion("cuTensorMapEncodeTiled", &fnp, 12000,
                                     cudaEnableDefault, &st);
    PFN_tmapEncode enc = (PFN_tmapEncode)fnp;

    CUtensorMap a_map, b_map;
    {
        cuuint64_t dims[2]    = { DIN, NTOK };
        cuuint64_t strides[1] = { DIN * sizeof(__half) };    // 1024 B
        cuuint32_t box[2]     = { KC, TILE_M };              // 64 x 128
        cuuint32_t es[2]      = { 1, 1 };
        enc(&a_map, CU_TENSOR_MAP_DATA_TYPE_UINT16, 2, xh_ptr,
            dims, strides, box, es,
            CU_TENSOR_MAP_INTERLEAVE_NONE, CU_TENSOR_MAP_SWIZZLE_128B,
            CU_TENSOR_MAP_L2_PROMOTION_L2_128B, CU_TENSOR_MAP_FLOAT_OOB_FILL_NONE);
    }
    {
        cuuint64_t dims[2]    = { KEXP * DIN, DOUT };        // 4096 x 512
        cuuint64_t strides[1] = { KEXP * DIN * sizeof(__half) };  // 8192 B
        cuuint32_t box[2]     = { KC, TILE_N };              // 64 x 64
        cuuint32_t es[2]      = { 1, 1 };
        enc(&b_map, CU_TENSOR_MAP_DATA_TYPE_UINT16, 2, wc_ptr,
            dims, strides, box, es,
            CU_TENSOR_MAP_INTERLEAVE_NONE, CU_TENSOR_MAP_SWIZZLE_128B,
            CU_TENSOR_MAP_L2_PROMOTION_L2_128B, CU_TENSOR_MAP_FLOAT_OOB_FILL_NONE);
    }

    cudaFuncSetAttribute(moe_gemm_kernel, cudaFuncAttributeMaxDynamicSharedMemorySize, DYN_BYTES);
    dim3 grid(DOUT / TILE_N, NTOK / TILE_M, KEXP / EPC);   // (8, 128, 4) = 4096 CTAs
    moe_gemm_kernel<<<grid, 256, DYN_BYTES>>>(a_map, b_map, bz, out);
}

// round 12
// speedup vs baseline: 1.1256x; 1.1256x over previous
#include <cuda_runtime.h>
#include <cuda.h>
#include <cuda_fp16.h>
#include <cstdint>

// ---------------- problem constants ----------------
#define NTOK   16384
#define DIN    512
#define DOUT   512
#define KEXP   8
#define KC     64              // fp16 elems per K chunk = 128 B (SW128 atom)
#define TILE_M 128
#define TILE_N 64
#define EPC    4               // experts per CTA (kz = 2)  -- proven R8 config
#define NCHJ   8               // K chunks per expert (512/64)
#define A_BYTES  (TILE_M * 128)     // 16 KB
#define B_BYTES  (TILE_N * 128)     // 8 KB
#define NSA      2                  // A ring stages
#define NSB      8                  // B ring stages (2 groups x 4 experts)
#define DYN_BYTES (NSA * A_BYTES + NSB * B_BYTES + 1024)   // ~97 KB -> 2 CTAs/SM

// ---------------- device scratch ----------------
__device__ __half g_xh[(size_t)NTOK * DIN];        // fp16 unscaled x
__device__ float  g_coeffs[NTOK * KEXP];           // gating coeffs
__device__ __half g_wc[(size_t)DOUT * (KEXP*DIN)]; // fp16 stacked weights [o][e*512+i]

// ---------------- PTX helpers (sm_90-baseline; NO tcgen05) ----------------
__device__ __forceinline__ uint32_t smem_u32(const void* p) {
    uint32_t a;
    asm("{ .reg .u64 t; cvta.to.shared.u64 t, %1; cvt.u32.u64 %0, t; }" : "=r"(a) : "l"(p));
    return a;
}

#define MBAR_INIT(addr, cnt) \
    asm volatile("mbarrier.init.shared.b64 [%0], %1;" :: "r"(addr), "r"(cnt) : "memory")
#define MBAR_EXPECT_TX(addr, bytes) \
    asm volatile("mbarrier.arrive.expect_tx.shared.b64 _, [%0], %1;" :: "r"(addr), "r"(bytes) : "memory")
#define MBAR_ARRIVE(addr) \
    asm volatile("mbarrier.arrive.shared.b64 _, [%0];" :: "r"(addr) : "memory")

#define MBAR_WAIT(addr, parity) do {                                              \
    uint32_t _m = (uint32_t)(addr);                                               \
    uint32_t _p = (uint32_t)(parity);                                             \
    uint32_t _done;                                                               \
    asm volatile("{\n\t.reg .pred p;\n\t"                                         \
        "mbarrier.try_wait.parity.acquire.cta.shared::cta.b64 p, [%1], %2;\n\t"   \
        "selp.b32 %0, 1, 0, p;\n\t}"                                              \
        : "=r"(_done) : "r"(_m), "r"(_p) : "memory");                             \
    if (!_done) {                                                                 \
        asm volatile("{\n\t.reg .pred P1;\n\t"                                    \
            "WAIT_LOOP_%=:\n\t"                                                   \
            "mbarrier.try_wait.parity.acquire.cta.shared::cta.b64 P1, [%0], %1, 0x989680;\n\t" \
            "@P1 bra.uni WAIT_DONE_%=;\n\t"                                       \
            "bra.uni WAIT_LOOP_%=;\n\t"                                           \
            "WAIT_DONE_%=:\n\t}"                                                  \
            :: "r"(_m), "r"(_p) : "memory");                                      \
    }                                                                             \
} while (0)

#define TMA2D(dst, map, cx, cy, bar) \
    asm volatile("cp.async.bulk.tensor.2d.shared::cta.global.tile.mbarrier::complete_tx::bytes " \
        "[%0], [%1, {%2, %3}], [%4];" \
        :: "r"(dst), "l"(map), "r"(cx), "r"(cy), "r"(bar) : "memory")

#define LDSM_X4(r, addr) \
    asm volatile("ldmatrix.sync.aligned.m8n8.x4.shared.b16 {%0,%1,%2,%3}, [%4];" \
        : "=r"((r)[0]), "=r"((r)[1]), "=r"((r)[2]), "=r"((r)[3]) : "r"(addr))

__device__ __forceinline__ uint32_t hmul2(uint32_t a, uint32_t b) {
    uint32_t d;
    asm("mul.rn.f16x2 %0, %1, %2;" : "=r"(d) : "r"(a), "r"(b));
    return d;
}

__device__ __forceinline__ void mma16816(float* d, const uint32_t* a, const uint32_t* b) {
    asm volatile("mma.sync.aligned.m16n8k16.row.col.f32.f16.f16.f32 "
        "{%0,%1,%2,%3}, {%4,%5,%6,%7}, {%8,%9}, {%0,%1,%2,%3};"
        : "+f"(d[0]), "+f"(d[1]), "+f"(d[2]), "+f"(d[3])
        : "r"(a[0]), "r"(a[1]), "r"(a[2]), "r"(a[3]), "r"(b[0]), "r"(b[1]));
}

// ---------------- kernel 1: FUSED prep ----------------
// blocks [0, 2048)        : gating softmax + fp16 convert of x  (8 tokens/block)
// blocks [2048, 2560)     : weight pack to fp16 + zero a slice of out
// The weight-pack blocks are pure DRAM streaming and overlap with the
// latency-bound gating blocks (gating DRAM util was only 16.8%).
__global__ void __launch_bounds__(256) prep_fused_kernel(
    const float* __restrict__ x,
    const float* __restrict__ mixer_w,
    const float* __restrict__ mixer_b,
    const float* __restrict__ W,
    float4* __restrict__ out4)
{
    const int tid = threadIdx.x;

    if (blockIdx.x >= 2048) {
        // ---- weight pack + output zero ----
        const int o = blockIdx.x - 2048;
        __half* orow = g_wc + (size_t)o * (KEXP * DIN);
        #pragma unroll
        for (int e = 0; e < KEXP; e++) {
            const float* src = W + ((size_t)e * DOUT + o) * DIN;
            #pragma unroll
            for (int i = 0; i < DIN / 256; i++)
                orow[e * DIN + i * 256 + tid] = __float2half_rn(src[i * 256 + tid]);
        }
        // zero out: 16384*512 floats = 2,097,152 float4 over 512 blocks
        const size_t zbase = (size_t)o * 4096 + tid;
        #pragma unroll
        for (int i = 0; i < 16; i++)
            out4[zbase + i * 256] = make_float4(0.f, 0.f, 0.f, 0.f);
        return;
    }

    // ---- gating softmax + x convert ----
    __shared__ float sw[KEXP * DIN];
    __shared__ float sb[KEXP];
    for (int i = tid; i < KEXP * DIN; i += 256) sw[i] = mixer_w[i];
    if (tid < KEXP) sb[tid] = mixer_b[tid];
    __syncthreads();

    const int warp = tid >> 5, lane = tid & 31;
    const int t = blockIdx.x * 8 + warp;
    const float2* xr2 = reinterpret_cast<const float2*>(x + (size_t)t * DIN);

    float2 xv[8];
    #pragma unroll
    for (int ii = 0; ii < 8; ii++) xv[ii] = xr2[ii * 32 + lane];

    float acc[KEXP];
    #pragma unroll
    for (int e = 0; e < KEXP; e++) acc[e] = 0.f;
    #pragma unroll
    for (int ii = 0; ii < 8; ii++) {
        const int i = ii * 64 + lane * 2;
        #pragma unroll
        for (int e = 0; e < KEXP; e++)
            acc[e] += xv[ii].x * sw[e * DIN + i] + xv[ii].y * sw[e * DIN + i + 1];
    }
    #pragma unroll
    for (int off = 16; off > 0; off >>= 1) {
        #pragma unroll
        for (int e = 0; e < KEXP; e++)
            acc[e] += __shfl_xor_sync(0xffffffffu, acc[e], off);
    }
    float lg[KEXP];
    #pragma unroll
    for (int e = 0; e < KEXP; e++) lg[e] = acc[e] + sb[e];
    float mx = lg[0];
    #pragma unroll
    for (int e = 1; e < KEXP; e++) mx = fmaxf(mx, lg[e]);
    float p[KEXP], s = 0.f;
    #pragma unroll
    for (int e = 0; e < KEXP; e++) { p[e] = __expf(lg[e] - mx); s += p[e]; }
    const float inv = 1.f / s;

    __half2* dst = reinterpret_cast<__half2*>(g_xh + (size_t)t * DIN);
    #pragma unroll
    for (int ii = 0; ii < 8; ii++)
        dst[ii * 32 + lane] = __floats2half2_rn(xv[ii].x, xv[ii].y);

    #pragma unroll
    for (int e = 0; e < KEXP; e++)
        if (lane == e) g_coeffs[(size_t)t * KEXP + e] = p[e] * inv;
}

// ---------------- kernel 2: fused 4-expert GEMM (proven R8 config) ----------------
// acc accumulates Sigma_e c_e*(A B_e^T) directly: A frags loaded once per K-chunk,
// scaled per expert by half2 coeff (mul.f16x2), MMA'd into ONE fp32 accumulator.
// Bias added exactly (fp32) in epilogue; kz halves reduced via 2 deterministic atomicAdds.
__global__ void __launch_bounds__(256, 2) moe_gemm_kernel(
    const __grid_constant__ CUtensorMap a_map,     // g_xh  [16384, 512]
    const __grid_constant__ CUtensorMap b_map,     // g_wc  [512, 4096]
    const float* __restrict__ bz,                  // [8, 512]
    float* __restrict__ out)
{
    extern __shared__ char dyn_smem[];
    __shared__ __align__(8) unsigned long long s_bars[2 * NSA + 2 * NSB];
    __shared__ float s_coef[TILE_M * EPC];         // [128][4] this CTA's experts
    __shared__ float s_bias[EPC * TILE_N];         // [4][64]

    const int tid = threadIdx.x;
    const int w   = tid >> 5;
    const int l   = tid & 31;
    const int ntile = blockIdx.x;    // 0..7
    const int mtile = blockIdx.y;    // 0..127
    const int kz    = blockIdx.z;    // 0..1  -> experts kz*4 .. kz*4+3

    const uint32_t base = (smem_u32(dyn_smem) + 1023u) & ~1023u;
    const uint32_t As = base;                       // A ring: 2 x 16 KB
    const uint32_t Bs = base + NSA * A_BYTES;       // B ring: 8 x 8 KB
    const uint32_t bars = smem_u32(s_bars);
    const uint32_t AF = bars;                 // A full  [2]
    const uint32_t AE = bars + NSA * 8;       // A empty [2]
    const uint32_t BF = bars + 2 * NSA * 8;   // B full  [8]
    const uint32_t BE = BF + NSB * 8;         // B empty [8]

    if (tid == 0) {
        #pragma unroll
        for (int s = 0; s < NSA; s++) { MBAR_INIT(AF + s * 8, 1); MBAR_INIT(AE + s * 8, 8); }
        #pragma unroll
        for (int s = 0; s < NSB; s++) { MBAR_INIT(BF + s * 8, 1); MBAR_INIT(BE + s * 8, 8); }
    }
    for (int i = tid; i < TILE_M * EPC; i += 256)
        s_coef[i] = g_coeffs[(mtile * TILE_M + (i >> 2)) * KEXP + kz * EPC + (i & 3)];
    for (int i = tid; i < EPC * TILE_N; i += 256)
        s_bias[i] = bz[(kz * EPC + (i >> 6)) * DOUT + ntile * TILE_N + (i & 63)];
    __syncthreads();

    if (tid == 0) {
        #pragma unroll
        for (int s = 0; s < NSA; s++) {          // A chunks 0,1
            MBAR_EXPECT_TX(AF + s * 8, A_BYTES);
            TMA2D(As + s * A_BYTES, &a_map, s * KC, mtile * TILE_M, AF + s * 8);
        }
        #pragma unroll
        for (int bi = 0; bi < NSB; bi++) {       // B (chunk j=bi>>2, expert ei=bi&3)
            MBAR_EXPECT_TX(BF + bi * 8, B_BYTES);
            TMA2D(Bs + bi * B_BYTES, &b_map,
                  ((kz * EPC + (bi & 3)) * NCHJ + (bi >> 2)) * KC, ntile * TILE_N, BF + bi * 8);
        }
    }

    // warp layout: 4 (M) x 2 (N); warp tile 32x32
    const int wm = (w & 3) * 32;
    const int wn = (w >> 2) * 32;
    int rA[2], rB[2];
    #pragma unroll
    for (int mi = 0; mi < 2; mi++) rA[mi] = wm + mi * 16 + (l & 15);
    #pragma unroll
    for (int nj2 = 0; nj2 < 2; nj2++)
        rB[nj2] = wn + nj2 * 16 + ((l >> 4) & 1) * 8 + (l & 7);
    const int segA = (l >> 4);
    const int segB = (l >> 3) & 1;

    // per-expert per-row half2 coeffs: ch[ei][mi][h]  row = wm+mi*16+(l>>2)+h*8
    uint32_t ch[EPC][2][2];
    #pragma unroll
    for (int ei = 0; ei < EPC; ei++)
        #pragma unroll
        for (int mi = 0; mi < 2; mi++)
            #pragma unroll
            for (int h = 0; h < 2; h++) {
                const int r = wm + mi * 16 + (l >> 2) + h * 8;
                const __half hv = __float2half_rn(s_coef[r * EPC + ei]);
                const __half2 h2 = __half2half2(hv);
                ch[ei][mi][h] = *reinterpret_cast<const uint32_t*>(&h2);
            }

    float acc[2][4][4];
    #pragma unroll
    for (int mi = 0; mi < 2; mi++)
        #pragma unroll
        for (int nj = 0; nj < 4; nj++)
            #pragma unroll
            for (int q = 0; q < 4; q++) acc[mi][nj][q] = 0.f;

    #pragma unroll 1
    for (int j = 0; j < NCHJ; j++) {
        const int sa   = j & 1;
        const int sgrp = (j & 1) * 4;
        const uint32_t ph = (uint32_t)((j >> 1) & 1);
        const uint32_t Ab = As + sa * A_BYTES;

        MBAR_WAIT(AF + sa * 8, ph);
        #pragma unroll
        for (int ei = 0; ei < EPC; ei++) MBAR_WAIT(BF + (sgrp + ei) * 8, ph);

        #pragma unroll
        for (int kk = 0; kk < 4; kk++) {
            const int s0 = kk * 2;
            uint32_t ar[2][4];
            #pragma unroll
            for (int mi = 0; mi < 2; mi++) {
                uint32_t addr = Ab + rA[mi] * 128 +
                    ((uint32_t)((s0 + segA) ^ (rA[mi] & 7)) << 4);
                LDSM_X4(ar[mi], addr);
            }
            #pragma unroll
            for (int ei = 0; ei < EPC; ei++) {
                const uint32_t Bb = Bs + (sgrp + ei) * B_BYTES;
                uint32_t br[2][4];
                #pragma unroll
                for (int nj2 = 0; nj2 < 2; nj2++) {
                    uint32_t addr = Bb + rB[nj2] * 128 +
                        ((uint32_t)((s0 + segB) ^ (rB[nj2] & 7)) << 4);
                    LDSM_X4(br[nj2], addr);
                }
                #pragma unroll
                for (int mi = 0; mi < 2; mi++) {
                    uint32_t as[4];
                    as[0] = hmul2(ar[mi][0], ch[ei][mi][0]);
                    as[1] = hmul2(ar[mi][1], ch[ei][mi][1]);
                    as[2] = hmul2(ar[mi][2], ch[ei][mi][0]);
                    as[3] = hmul2(ar[mi][3], ch[ei][mi][1]);
                    #pragma unroll
                    for (int nj = 0; nj < 4; nj++)
                        mma16816(acc[mi][nj], as, &br[nj >> 1][(nj & 1) * 2]);
                }
            }
        }

        if (l == 0) {
            MBAR_ARRIVE(AE + sa * 8);
            #pragma unroll
            for (int ei = 0; ei < EPC; ei++) MBAR_ARRIVE(BE + (sgrp + ei) * 8);
        }
        if (tid == 0 && j + 2 < NCHJ) {
            const int jn = j + 2;
            MBAR_WAIT(AE + sa * 8, ph);
            MBAR_EXPECT_TX(AF + sa * 8, A_BYTES);
            TMA2D(Ab, &a_map, jn * KC, mtile * TILE_M, AF + sa * 8);
            #pragma unroll
            for (int ei = 0; ei < EPC; ei++) {
                MBAR_WAIT(BE + (sgrp + ei) * 8, ph);
                MBAR_EXPECT_TX(BF + (sgrp + ei) * 8, B_BYTES);
                TMA2D(Bs + (sgrp + ei) * B_BYTES, &b_map,
                      ((kz * EPC + ei) * NCHJ + jn) * KC, ntile * TILE_N, BF + (sgrp + ei) * 8);
            }
        }
    }

    // epilogue: + Sigma_e c_e(row)*b_e(col) in fp32, then 2-way split-expert atomic reduce
    const int row0 = mtile * TILE_M + wm + (l >> 2);
    const int col0 = ntile * TILE_N + wn + 2 * (l & 3);
    #pragma unroll
    for (int mi = 0; mi < 2; mi++) {
        const int rl = wm + mi * 16 + (l >> 2);
        float cl[EPC], chh[EPC];
        #pragma unroll
        for (int e = 0; e < EPC; e++) {
            cl[e]  = s_coef[rl * EPC + e];
            chh[e] = s_coef[(rl + 8) * EPC + e];
        }
        #pragma unroll
        for (int nj = 0; nj < 4; nj++) {
            const int cc = wn + nj * 8 + 2 * (l & 3);
            float bl0 = 0.f, bl1 = 0.f, bh0 = 0.f, bh1 = 0.f;
            #pragma unroll
            for (int e = 0; e < EPC; e++) {
                const float b0 = s_bias[e * TILE_N + cc];
                const float b1 = s_bias[e * TILE_N + cc + 1];
                bl0 += cl[e] * b0;  bl1 += cl[e] * b1;
                bh0 += chh[e] * b0; bh1 += chh[e] * b1;
            }
            const int gr = row0 + mi * 16;
            const int gc = col0 + nj * 8;
            atomicAdd(&out[(size_t)gr * DOUT + gc],           acc[mi][nj][0] + bl0);
            atomicAdd(&out[(size_t)gr * DOUT + gc + 1],       acc[mi][nj][1] + bl1);
            atomicAdd(&out[(size_t)(gr + 8) * DOUT + gc],     acc[mi][nj][2] + bh0);
            atomicAdd(&out[(size_t)(gr + 8) * DOUT + gc + 1], acc[mi][nj][3] + bh1);
        }
    }
}

// ---------------- host launcher ----------------
typedef CUresult (*PFN_tmapEncode)(
    CUtensorMap*, CUtensorMapDataType, cuuint32_t, void*,
    const cuuint64_t*, const cuuint64_t*, const cuuint32_t*, const cuuint32_t*,
    CUtensorMapInterleave, CUtensorMapSwizzle, CUtensorMapL2promotion, CUtensorMapFloatOOBfill);

extern "C" void kernel_launch(void* const* d_in, const int* in_sizes, int n_in,
                              void* d_out, int out_size)
{
    const float* x  = (const float*)d_in[0];   // [16384, 512]
    const float* W  = (const float*)d_in[1];   // [8, 512, 512]
    const float* bz = (const float*)d_in[2];   // [8, 512]
    const float* mw = (const float*)d_in[3];   // [8, 512]
    const float* mb = (const float*)d_in[4];   // [8]
    float* out = (float*)d_out;
    (void)in_sizes; (void)n_in; (void)out_size;

    void* xh_ptr = nullptr; void* wc_ptr = nullptr;
    cudaGetSymbolAddress(&xh_ptr, g_xh);
    cudaGetSymbolAddress(&wc_ptr, g_wc);

    // fused prep: gating + x convert (blocks 0..2047), W pack + out zero (2048..2559)
    prep_fused_kernel<<<2560, 256>>>(x, mw, mb, W, (float4*)out);

    void* fnp = nullptr;
    cudaDriverEntryPointQueryResult st;
    cudaGetDriverEntryPointByVersion("cuTensorMapEncodeTiled", &fnp, 12000,
                                     cudaEnableDefault, &st);
    PFN_tmapEncode enc = (PFN_tmapEncode)fnp;

    CUtensorMap a_map, b_map;
    {
        cuuint64_t dims[2]    = { DIN, NTOK };
        cuuint64_t strides[1] = { DIN * sizeof(__half) };    // 1024 B
        cuuint32_t box[2]     = { KC, TILE_M };              // 64 x 128
        cuuint32_t es[2]      = { 1, 1 };
        enc(&a_map, CU_TENSOR_MAP_DATA_TYPE_UINT16, 2, xh_ptr,
            dims, strides, box, es,
            CU_TENSOR_MAP_INTERLEAVE_NONE, CU_TENSOR_MAP_SWIZZLE_128B,
            CU_TENSOR_MAP_L2_PROMOTION_L2_128B, CU_TENSOR_MAP_FLOAT_OOB_FILL_NONE);
    }
    {
        cuuint64_t dims[2]    = { KEXP * DIN, DOUT };        // 4096 x 512
        cuuint64_t strides[1] = { KEXP * DIN * sizeof(__half) };  // 8192 B
        cuuint32_t box[2]     = { KC, TILE_N };              // 64 x 64
        cuuint32_t es[2]      = { 1, 1 };
        enc(&b_map, CU_TENSOR_MAP_DATA_TYPE_UINT16, 2, wc_ptr,
            dims, strides, box, es,
            CU_TENSOR_MAP_INTERLEAVE_NONE, CU_TENSOR_MAP_SWIZZLE_128B,
            CU_TENSOR_MAP_L2_PROMOTION_L2_128B, CU_TENSOR_MAP_FLOAT_OOB_FILL_NONE);
    }

    cudaFuncSetAttribute(moe_gemm_kernel, cudaFuncAttributeMaxDynamicSharedMemorySize, DYN_BYTES);
    dim3 grid(DOUT / TILE_N, NTOK / TILE_M, 2);   // (8, 128, 2) = 2048 CTAs
    moe_gemm_kernel<<<grid, 256, DYN_BYTES>>>(a_map, b_map, bz, out);
}